// round 2
// baseline (speedup 1.0000x reference)
#include <cuda_runtime.h>
#include <cuda_bf16.h>
#include <cstdint>

#define HIDDEN   5120
#define NEXP     160
#define NGROUP   8
#define EPG      20      // experts per group
#define TOPK     6

#define BM       128
#define BN       160
#define BK       16
#define NTHREADS 256
#define KTILES   (HIDDEN / BK)   // 320
#define LSTR     161             // logits smem row stride (odd -> conflict-free)

#define SMEM_BYTES (BM * LSTR * 4)   // 82432; >= GEMM staging (18432)

#define NEG_INF (-__int_as_float(0x7f800000))

// ---- packed f32x2 helpers (sm_103a) ----
__device__ __forceinline__ void fma2(unsigned long long& d,
                                     unsigned long long a,
                                     unsigned long long b) {
    asm("fma.rn.f32x2 %0, %1, %2, %0;" : "+l"(d) : "l"(a), "l"(b));
}
__device__ __forceinline__ unsigned long long pack2(float x) {
    unsigned long long r;
    unsigned u = __float_as_uint(x);
    asm("mov.b64 %0, {%1, %1};" : "=l"(r) : "r"(u));
    return r;
}
__device__ __forceinline__ void unpack2(unsigned long long v, float& lo, float& hi) {
    unsigned a, b;
    asm("mov.b64 {%0, %1}, %2;" : "=r"(a), "=r"(b) : "l"(v));
    lo = __uint_as_float(a);
    hi = __uint_as_float(b);
}

extern "C" __global__ void __launch_bounds__(NTHREADS, 1)
moe_gate_kernel(const float* __restrict__ X,   // [T, HIDDEN]
                const float* __restrict__ W,   // [NEXP, HIDDEN]
                float* __restrict__ out,       // [T*6 idx][T*6 weights]
                int T)
{
    extern __shared__ float smem[];
    float* As = smem;               // [BK][BM]
    float* Bs = smem + BK * BM;     // [BK][BN]
    float* logits = smem;           // reused after GEMM: [BM][LSTR]

    const int tid  = threadIdx.x;
    const int tm   = tid >> 4;      // 0..15 -> 8 token rows each
    const int tn   = tid & 15;      // 0..15 -> 10 expert cols each
    const int row0 = blockIdx.x * BM;

    // accumulators: 8 m-rows x 5 n-pairs (f32x2)
    unsigned long long acc[8][5];
#pragma unroll
    for (int i = 0; i < 8; i++)
#pragma unroll
        for (int j = 0; j < 5; j++) acc[i][j] = 0ull;

    // ---- global load mapping ----
    // A tile: 128x16 floats = 512 float4; thread loads (tid), (tid+256)
    const int ar0 = tid >> 2,         ac0 = (tid & 3);
    const int ar1 = (tid + 256) >> 2, ac1 = ((tid + 256) & 3);
    // B tile: 160x16 floats = 640 float4; thread loads tid, tid+256, tid+512(<640)
    const int bi0 = tid,       br0 = bi0 >> 2, bc0 = bi0 & 3;
    const int bi1 = tid + 256, br1 = bi1 >> 2, bc1 = bi1 & 3;
    const int bi2 = tid + 512, br2 = bi2 >> 2, bc2 = bi2 & 3;
    const bool bpred2 = (bi2 < 640);

    const float* Arow0 = X + (size_t)(row0 + ar0) * HIDDEN;
    const float* Arow1 = X + (size_t)(row0 + ar1) * HIDDEN;
    const float* Brow0 = W + (size_t)br0 * HIDDEN;
    const float* Brow1 = W + (size_t)br1 * HIDDEN;
    const float* Brow2 = W + (size_t)br2 * HIDDEN;

    float4 aS0, aS1, bS0, bS1, bS2;
    bS2 = make_float4(0.f, 0.f, 0.f, 0.f);

    // prefetch tile 0
    {
        const int k0 = 0;
        aS0 = *(const float4*)(Arow0 + k0 + ac0 * 4);
        aS1 = *(const float4*)(Arow1 + k0 + ac1 * 4);
        bS0 = *(const float4*)(Brow0 + k0 + bc0 * 4);
        bS1 = *(const float4*)(Brow1 + k0 + bc1 * 4);
        if (bpred2) bS2 = *(const float4*)(Brow2 + k0 + bc2 * 4);
    }

    for (int kt = 0; kt < KTILES; ++kt) {
        __syncthreads();   // previous compute done before smem overwrite
        // ---- stage into smem (k-major) ----
        As[(ac0 * 4 + 0) * BM + ar0] = aS0.x;
        As[(ac0 * 4 + 1) * BM + ar0] = aS0.y;
        As[(ac0 * 4 + 2) * BM + ar0] = aS0.z;
        As[(ac0 * 4 + 3) * BM + ar0] = aS0.w;
        As[(ac1 * 4 + 0) * BM + ar1] = aS1.x;
        As[(ac1 * 4 + 1) * BM + ar1] = aS1.y;
        As[(ac1 * 4 + 2) * BM + ar1] = aS1.z;
        As[(ac1 * 4 + 3) * BM + ar1] = aS1.w;

        Bs[(bc0 * 4 + 0) * BN + br0] = bS0.x;
        Bs[(bc0 * 4 + 1) * BN + br0] = bS0.y;
        Bs[(bc0 * 4 + 2) * BN + br0] = bS0.z;
        Bs[(bc0 * 4 + 3) * BN + br0] = bS0.w;
        Bs[(bc1 * 4 + 0) * BN + br1] = bS1.x;
        Bs[(bc1 * 4 + 1) * BN + br1] = bS1.y;
        Bs[(bc1 * 4 + 2) * BN + br1] = bS1.z;
        Bs[(bc1 * 4 + 3) * BN + br1] = bS1.w;
        if (bpred2) {
            Bs[(bc2 * 4 + 0) * BN + br2] = bS2.x;
            Bs[(bc2 * 4 + 1) * BN + br2] = bS2.y;
            Bs[(bc2 * 4 + 2) * BN + br2] = bS2.z;
            Bs[(bc2 * 4 + 3) * BN + br2] = bS2.w;
        }
        __syncthreads();

        // ---- prefetch next tile (latency hidden under compute) ----
        if (kt + 1 < KTILES) {
            const int k0 = (kt + 1) * BK;
            aS0 = *(const float4*)(Arow0 + k0 + ac0 * 4);
            aS1 = *(const float4*)(Arow1 + k0 + ac1 * 4);
            bS0 = *(const float4*)(Brow0 + k0 + bc0 * 4);
            bS1 = *(const float4*)(Brow1 + k0 + bc1 * 4);
            if (bpred2) bS2 = *(const float4*)(Brow2 + k0 + bc2 * 4);
        }

        // ---- compute: 16 k-steps, 8x10 outer product (as 8x5 f32x2) ----
#pragma unroll
        for (int kk = 0; kk < BK; ++kk) {
            const float4 a01 = *(const float4*)&As[kk * BM + tm * 8];
            const float4 a23 = *(const float4*)&As[kk * BM + tm * 8 + 4];
            unsigned long long pa[8];
            pa[0] = pack2(a01.x); pa[1] = pack2(a01.y);
            pa[2] = pack2(a01.z); pa[3] = pack2(a01.w);
            pa[4] = pack2(a23.x); pa[5] = pack2(a23.y);
            pa[6] = pack2(a23.z); pa[7] = pack2(a23.w);

            const unsigned long long* bp =
                (const unsigned long long*)&Bs[kk * BN + tn * 10];
            const unsigned long long b0 = bp[0], b1 = bp[1], b2 = bp[2],
                                     b3 = bp[3], b4 = bp[4];
#pragma unroll
            for (int i = 0; i < 8; i++) {
                fma2(acc[i][0], pa[i], b0);
                fma2(acc[i][1], pa[i], b1);
                fma2(acc[i][2], pa[i], b2);
                fma2(acc[i][3], pa[i], b3);
                fma2(acc[i][4], pa[i], b4);
            }
        }
    }

    // ---- epilogue: logits to smem ----
    __syncthreads();
#pragma unroll
    for (int i = 0; i < 8; i++) {
        const int r = tm * 8 + i;
#pragma unroll
        for (int j = 0; j < 5; j++) {
            float lo, hi;
            unpack2(acc[i][j], lo, hi);
            logits[r * LSTR + tn * 10 + 2 * j]     = lo;
            logits[r * LSTR + tn * 10 + 2 * j + 1] = hi;
        }
    }
    __syncthreads();

    // ---- gating: one thread per token ----
    if (tid < BM) {
        const int t = row0 + tid;
        if (t < T) {
            const float* row = logits + tid * LSTR;

            // group maxima over raw logits (softmax is monotone)
            float gmax[NGROUP];
            float m = NEG_INF;
#pragma unroll
            for (int g = 0; g < NGROUP; g++) {
                float gm = NEG_INF;
#pragma unroll
                for (int j = 0; j < EPG; j++)
                    gm = fmaxf(gm, row[g * EPG + j]);
                gmax[g] = gm;
                m = fmaxf(m, gm);
            }

            // top-3 groups (strict >, ascending scan => lower index wins ties)
            float v0 = NEG_INF, v1 = NEG_INF, v2 = NEG_INF;
            int g0 = 0, g1 = 0, g2 = 0;
#pragma unroll
            for (int g = 0; g < NGROUP; g++) {
                const float v = gmax[g];
                if (v > v0)      { v2 = v1; g2 = g1; v1 = v0; g1 = g0; v0 = v; g0 = g; }
                else if (v > v1) { v2 = v1; g2 = g1; v1 = v;  g1 = g; }
                else if (v > v2) { v2 = v;  g2 = g; }
            }
            const unsigned gm_mask = (1u << g0) | (1u << g1) | (1u << g2);

            // top-6 experts among allowed groups (stable insertion on raw logits)
            float tv0 = NEG_INF, tv1 = NEG_INF, tv2 = NEG_INF;
            float tv3 = NEG_INF, tv4 = NEG_INF, tv5 = NEG_INF;
            int ti0 = -1, ti1 = -1, ti2 = -1, ti3 = -1, ti4 = -1, ti5 = -1;
#pragma unroll 1
            for (int g = 0; g < NGROUP; g++) {
                if (!((gm_mask >> g) & 1u)) continue;
#pragma unroll 1
                for (int j = 0; j < EPG; j++) {
                    const int e = g * EPG + j;
                    const float v = row[e];
                    if (v > tv5) {
                        if (v > tv4) { tv5 = tv4; ti5 = ti4;
                            if (v > tv3) { tv4 = tv3; ti4 = ti3;
                                if (v > tv2) { tv3 = tv2; ti3 = ti2;
                                    if (v > tv1) { tv2 = tv1; ti2 = ti1;
                                        if (v > tv0) { tv1 = tv0; ti1 = ti0; tv0 = v; ti0 = e; }
                                        else          { tv1 = v;  ti1 = e; }
                                    } else { tv2 = v; ti2 = e; }
                                } else { tv3 = v; ti3 = e; }
                            } else { tv4 = v; ti4 = e; }
                        } else { tv5 = v; ti5 = e; }
                    }
                }
            }

            // normalized weights: exp(l - m) / (sum_top6 + eps); softmax Z cancels
            const float w0 = expf(tv0 - m), w1 = expf(tv1 - m), w2 = expf(tv2 - m);
            const float w3 = expf(tv3 - m), w4 = expf(tv4 - m), w5 = expf(tv5 - m);
            const float inv = 1.0f / (w0 + w1 + w2 + w3 + w4 + w5 + 1e-20f);

            float* outIdx = out;
            float* outW   = out + (size_t)T * TOPK;
            const size_t base = (size_t)t * TOPK;
            outIdx[base + 0] = (float)ti0;  outW[base + 0] = w0 * inv;
            outIdx[base + 1] = (float)ti1;  outW[base + 1] = w1 * inv;
            outIdx[base + 2] = (float)ti2;  outW[base + 2] = w2 * inv;
            outIdx[base + 3] = (float)ti3;  outW[base + 3] = w3 * inv;
            outIdx[base + 4] = (float)ti4;  outW[base + 4] = w4 * inv;
            outIdx[base + 5] = (float)ti5;  outW[base + 5] = w5 * inv;
        }
    }
}

extern "C" void kernel_launch(void* const* d_in, const int* in_sizes, int n_in,
                              void* d_out, int out_size)
{
    const float* X = (const float*)d_in[0];
    const float* W = (const float*)d_in[1];
    const int T = in_sizes[0] / HIDDEN;   // 16384

    cudaFuncSetAttribute(moe_gate_kernel,
                         cudaFuncAttributeMaxDynamicSharedMemorySize, SMEM_BYTES);

    const int grid = (T + BM - 1) / BM;   // 128
    moe_gate_kernel<<<grid, NTHREADS, SMEM_BYTES>>>(X, W, (float*)d_out, T);
}

// round 4
// speedup vs baseline: 1.0004x; 1.0004x over previous
#include <cuda_runtime.h>
#include <cstdint>

#define HIDDEN   5120
#define NEXP     160
#define NGROUP   8
#define EPG      20
#define TOPK     6

#define BM       128
#define BK       16
#define NTHREADS 512
#define KTILES   (HIDDEN / BK)   // 320
#define LSTR     161

#define ASTR     132             // A smem row stride (floats), padded
#define BSTR     164             // B smem row stride (floats), padded
#define BUF_FLOATS (BK * ASTR + BK * BSTR)   // 2112 + 2624 = 4736

#define SMEM_BYTES (BM * LSTR * 4)   // 82432 >= 2*BUF_FLOATS*4 (37888)

#define NEG_INF (-__int_as_float(0x7f800000))

// ---- packed f32x2 helpers (sm_103a) ----
__device__ __forceinline__ void fma2(unsigned long long& d,
                                     unsigned long long a,
                                     unsigned long long b) {
    asm("fma.rn.f32x2 %0, %1, %2, %0;" : "+l"(d) : "l"(a), "l"(b));
}
__device__ __forceinline__ unsigned long long pack2(float x) {
    unsigned long long r;
    unsigned u = __float_as_uint(x);
    asm("mov.b64 %0, {%1, %1};" : "=l"(r) : "r"(u));
    return r;
}
__device__ __forceinline__ void unpack2(unsigned long long v, float& lo, float& hi) {
    unsigned a, b;
    asm("mov.b64 {%0, %1}, %2;" : "=r"(a), "=r"(b) : "l"(v));
    lo = __uint_as_float(a);
    hi = __uint_as_float(b);
}

extern "C" __global__ void __launch_bounds__(NTHREADS, 1)
moe_gate_kernel(const float* __restrict__ X,   // [T, HIDDEN]
                const float* __restrict__ W,   // [NEXP, HIDDEN]
                float* __restrict__ out,       // [T*6 idx][T*6 weights]
                int T)
{
    extern __shared__ float smem[];
    // ping-pong buffers; logits region reuses same smem after GEMM
    float* logits = smem;

    const int tid  = threadIdx.x;
    const int tm   = tid >> 4;      // 0..31 -> 4 token rows each
    const int tn   = tid & 15;      // 0..15 -> 10 expert cols each
    const int row0 = blockIdx.x * BM;

    // accumulators: 4 m-rows x 5 n-pairs (f32x2)
    unsigned long long acc[4][5];
#pragma unroll
    for (int i = 0; i < 4; i++)
#pragma unroll
        for (int j = 0; j < 5; j++) acc[i][j] = 0ull;

    // ---- global load mapping ----
    // A tile: 128x16 floats = 512 float4; thread loads idx = tid
    const int ar = tid >> 2, aq = tid & 3;
    // B tile: 160x16 floats = 640 float4; thread loads idx = tid, (+512 if tid<128)
    const int br0 = tid >> 2, bq0 = tid & 3;
    const int bi1 = tid + 512;
    const int br1 = bi1 >> 2, bq1 = bi1 & 3;
    const bool bpred = (bi1 < 640);

    const float* Arow = X + (size_t)(row0 + ar) * HIDDEN + aq * 4;
    const float* Brow0 = W + (size_t)br0 * HIDDEN + bq0 * 4;
    const float* Brow1 = W + (size_t)br1 * HIDDEN + bq1 * 4;

    float4 aS, bS0, bS1;
    bS1 = make_float4(0.f, 0.f, 0.f, 0.f);

    // prefetch tile 0
    aS  = *(const float4*)(Arow);
    bS0 = *(const float4*)(Brow0);
    if (bpred) bS1 = *(const float4*)(Brow1);

    for (int kt = 0; kt < KTILES; ++kt) {
        float* As = smem + (kt & 1) * BUF_FLOATS;
        float* Bs = As + BK * ASTR;

        // ---- stage prefetched regs into smem (k-major, padded strides) ----
        As[(aq * 4 + 0) * ASTR + ar] = aS.x;
        As[(aq * 4 + 1) * ASTR + ar] = aS.y;
        As[(aq * 4 + 2) * ASTR + ar] = aS.z;
        As[(aq * 4 + 3) * ASTR + ar] = aS.w;

        Bs[(bq0 * 4 + 0) * BSTR + br0] = bS0.x;
        Bs[(bq0 * 4 + 1) * BSTR + br0] = bS0.y;
        Bs[(bq0 * 4 + 2) * BSTR + br0] = bS0.z;
        Bs[(bq0 * 4 + 3) * BSTR + br0] = bS0.w;
        if (bpred) {
            Bs[(bq1 * 4 + 0) * BSTR + br1] = bS1.x;
            Bs[(bq1 * 4 + 1) * BSTR + br1] = bS1.y;
            Bs[(bq1 * 4 + 2) * BSTR + br1] = bS1.z;
            Bs[(bq1 * 4 + 3) * BSTR + br1] = bS1.w;
        }
        __syncthreads();   // single barrier per tile (ping-pong safe)

        // ---- prefetch next tile ----
        if (kt + 1 < KTILES) {
            const int k0 = (kt + 1) * BK;
            aS  = *(const float4*)(Arow + k0);
            bS0 = *(const float4*)(Brow0 + k0);
            if (bpred) bS1 = *(const float4*)(Brow1 + k0);
        }

        // ---- compute: 16 k-steps, 4x10 outer product (4x5 f32x2) ----
#pragma unroll
        for (int kk = 0; kk < BK; ++kk) {
            const float4 a4 = *(const float4*)&As[kk * ASTR + tm * 4];
            unsigned long long pa[4];
            pa[0] = pack2(a4.x); pa[1] = pack2(a4.y);
            pa[2] = pack2(a4.z); pa[3] = pack2(a4.w);

            const unsigned long long* bp =
                (const unsigned long long*)&Bs[kk * BSTR + tn * 10];
            const unsigned long long b0 = bp[0], b1 = bp[1], b2 = bp[2],
                                     b3 = bp[3], b4 = bp[4];
#pragma unroll
            for (int i = 0; i < 4; i++) {
                fma2(acc[i][0], pa[i], b0);
                fma2(acc[i][1], pa[i], b1);
                fma2(acc[i][2], pa[i], b2);
                fma2(acc[i][3], pa[i], b3);
                fma2(acc[i][4], pa[i], b4);
            }
        }
    }

    // ---- epilogue: logits to smem ----
    __syncthreads();
#pragma unroll
    for (int i = 0; i < 4; i++) {
        const int r = tm * 4 + i;
#pragma unroll
        for (int j = 0; j < 5; j++) {
            float lo, hi;
            unpack2(acc[i][j], lo, hi);
            logits[r * LSTR + tn * 10 + 2 * j]     = lo;
            logits[r * LSTR + tn * 10 + 2 * j + 1] = hi;
        }
    }
    __syncthreads();

    // ---- gating: one thread per token (verified round-2 code) ----
    if (tid < BM) {
        const int t = row0 + tid;
        if (t < T) {
            const float* row = logits + tid * LSTR;

            float gmax[NGROUP];
            float m = NEG_INF;
#pragma unroll
            for (int g = 0; g < NGROUP; g++) {
                float gm = NEG_INF;
#pragma unroll
                for (int j = 0; j < EPG; j++)
                    gm = fmaxf(gm, row[g * EPG + j]);
                gmax[g] = gm;
                m = fmaxf(m, gm);
            }

            float v0 = NEG_INF, v1 = NEG_INF, v2 = NEG_INF;
            int g0 = 0, g1 = 0, g2 = 0;
#pragma unroll
            for (int g = 0; g < NGROUP; g++) {
                const float v = gmax[g];
                if (v > v0)      { v2 = v1; g2 = g1; v1 = v0; g1 = g0; v0 = v; g0 = g; }
                else if (v > v1) { v2 = v1; g2 = g1; v1 = v;  g1 = g; }
                else if (v > v2) { v2 = v;  g2 = g; }
            }
            const unsigned gm_mask = (1u << g0) | (1u << g1) | (1u << g2);

            float tv0 = NEG_INF, tv1 = NEG_INF, tv2 = NEG_INF;
            float tv3 = NEG_INF, tv4 = NEG_INF, tv5 = NEG_INF;
            int ti0 = -1, ti1 = -1, ti2 = -1, ti3 = -1, ti4 = -1, ti5 = -1;
#pragma unroll 1
            for (int g = 0; g < NGROUP; g++) {
                if (!((gm_mask >> g) & 1u)) continue;
#pragma unroll 1
                for (int j = 0; j < EPG; j++) {
                    const int e = g * EPG + j;
                    const float v = row[e];
                    if (v > tv5) {
                        if (v > tv4) { tv5 = tv4; ti5 = ti4;
                            if (v > tv3) { tv4 = tv3; ti4 = ti3;
                                if (v > tv2) { tv3 = tv2; ti3 = ti2;
                                    if (v > tv1) { tv2 = tv1; ti2 = ti1;
                                        if (v > tv0) { tv1 = tv0; ti1 = ti0; tv0 = v; ti0 = e; }
                                        else          { tv1 = v;  ti1 = e; }
                                    } else { tv2 = v; ti2 = e; }
                                } else { tv3 = v; ti3 = e; }
                            } else { tv4 = v; ti4 = e; }
                        } else { tv5 = v; ti5 = e; }
                    }
                }
            }

            const float w0 = expf(tv0 - m), w1 = expf(tv1 - m), w2 = expf(tv2 - m);
            const float w3 = expf(tv3 - m), w4 = expf(tv4 - m), w5 = expf(tv5 - m);
            const float inv = 1.0f / (w0 + w1 + w2 + w3 + w4 + w5 + 1e-20f);

            float* outIdx = out;
            float* outW   = out + (size_t)T * TOPK;
            const size_t base = (size_t)t * TOPK;
            outIdx[base + 0] = (float)ti0;  outW[base + 0] = w0 * inv;
            outIdx[base + 1] = (float)ti1;  outW[base + 1] = w1 * inv;
            outIdx[base + 2] = (float)ti2;  outW[base + 2] = w2 * inv;
            outIdx[base + 3] = (float)ti3;  outW[base + 3] = w3 * inv;
            outIdx[base + 4] = (float)ti4;  outW[base + 4] = w4 * inv;
            outIdx[base + 5] = (float)ti5;  outW[base + 5] = w5 * inv;
        }
    }
}

extern "C" void kernel_launch(void* const* d_in, const int* in_sizes, int n_in,
                              void* d_out, int out_size)
{
    const float* X = (const float*)d_in[0];
    const float* W = (const float*)d_in[1];
    const int T = in_sizes[0] / HIDDEN;   // 16384

    cudaFuncSetAttribute(moe_gate_kernel,
                         cudaFuncAttributeMaxDynamicSharedMemorySize, SMEM_BYTES);

    const int grid = (T + BM - 1) / BM;   // 128
    moe_gate_kernel<<<grid, NTHREADS, SMEM_BYTES>>>(X, W, (float*)d_out, T);
}